// round 3
// baseline (speedup 1.0000x reference)
#include <cuda_runtime.h>
#include <mma.h>
#include <cstdint>
#include <cstddef>

using namespace nvcuda;

#define SEQL 512
#define NBATCH 64
#define ISZ 256
#define HSZ 1024
#define NGATES 4096  // 4*HSZ

// Scratch (device globals: no allocations allowed)
__device__ float g_P[(size_t)SEQL * NBATCH * NGATES];  // precomputed x-projections, 512MB
__device__ float g_c[NBATCH * HSZ];
__device__ float g_h0[NBATCH * HSZ];

// ---------------- cp.async helpers ----------------
__device__ __forceinline__ void cp16(void* smem, const void* gmem) {
    uint32_t s = (uint32_t)__cvta_generic_to_shared(smem);
    asm volatile("cp.async.cg.shared.global [%0], [%1], 16;\n" :: "r"(s), "l"(gmem));
}
__device__ __forceinline__ void cp_commit() { asm volatile("cp.async.commit_group;\n"); }
template<int N> __device__ __forceinline__ void cp_wait() {
    asm volatile("cp.async.wait_group %0;\n" :: "n"(N));
}

// ---------------- init: zero c and h0 ----------------
__global__ void init_kernel() {
    int i = blockIdx.x * blockDim.x + threadIdx.x;
    if (i < NBATCH * HSZ) { g_c[i] = 0.f; g_h0[i] = 0.f; }
}

// ---------------- phase 1: P[m][n] = sum_k x[m][k] * Wx[n][k] ----------------
// m = t*64+b (32768), n = gate*1024+u (4096), K=256. tf32 wmma, fp32 accum.
__global__ void __launch_bounds__(256) xproj_kernel(
    const float* __restrict__ x,
    const float* __restrict__ Wfx, const float* __restrict__ Wix,
    const float* __restrict__ Wgx, const float* __restrict__ Wox)
{
    constexpr int BM = 128, BN = 64, BK = 32;
    __shared__ __align__(16) float As[2][BM][BK];
    __shared__ __align__(16) float Bs[2][BN][BK];

    const int tid = threadIdx.x;
    const int m0 = blockIdx.x * BM;
    const int n0 = blockIdx.y * BN;

    const int gate = n0 >> 10;
    const float* Wsel = (gate == 0) ? Wfx : (gate == 1) ? Wix : (gate == 2) ? Wgx : Wox;
    const int u0 = n0 & (HSZ - 1);

    const int wid = tid >> 5;
    const int wm = wid & 3;   // 4 warps along M (32 rows each)
    const int wn = wid >> 2;  // 2 warps along N (32 cols each)

    wmma::fragment<wmma::accumulator, 16, 16, 8, float> acc[2][2];
    #pragma unroll
    for (int i = 0; i < 2; ++i)
        #pragma unroll
        for (int j = 0; j < 2; ++j) wmma::fill_fragment(acc[i][j], 0.f);

    auto load_chunk = [&](int st, int k0) {
        #pragma unroll
        for (int j = 0; j < 4; ++j) {                  // A: 128x32 = 1024 floats/4 = 256 vec4 *4
            int idx = tid + j * 256;                   // 0..1023
            int r = idx >> 3, c = (idx & 7) * 4;
            cp16(&As[st][r][c], x + (size_t)(m0 + r) * ISZ + k0 + c);
        }
        #pragma unroll
        for (int j = 0; j < 2; ++j) {                  // B: 64x32
            int idx = tid + j * 256;                   // 0..511
            int r = idx >> 3, c = (idx & 7) * 4;
            cp16(&Bs[st][r][c], Wsel + (size_t)(u0 + r) * ISZ + k0 + c);
        }
        cp_commit();
    };

    constexpr int NIT = ISZ / BK;  // 8
    load_chunk(0, 0);
    for (int kt = 0; kt < NIT; ++kt) {
        int cur = kt & 1;
        if (kt + 1 < NIT) { load_chunk(cur ^ 1, (kt + 1) * BK); cp_wait<1>(); }
        else              { cp_wait<0>(); }
        __syncthreads();
        #pragma unroll
        for (int kk = 0; kk < BK / 8; ++kk) {
            wmma::fragment<wmma::matrix_a, 16, 16, 8, wmma::precision::tf32, wmma::row_major> a[2];
            wmma::fragment<wmma::matrix_b, 16, 16, 8, wmma::precision::tf32, wmma::col_major> bb[2];
            #pragma unroll
            for (int i = 0; i < 2; ++i) {
                wmma::load_matrix_sync(a[i], &As[cur][wm * 32 + i * 16][kk * 8], BK);
                #pragma unroll
                for (int e = 0; e < a[i].num_elements; ++e)
                    a[i].x[e] = wmma::__float_to_tf32(a[i].x[e]);
            }
            #pragma unroll
            for (int j = 0; j < 2; ++j) {
                wmma::load_matrix_sync(bb[j], &Bs[cur][wn * 32 + j * 16][kk * 8], BK);
                #pragma unroll
                for (int e = 0; e < bb[j].num_elements; ++e)
                    bb[j].x[e] = wmma::__float_to_tf32(bb[j].x[e]);
            }
            #pragma unroll
            for (int i = 0; i < 2; ++i)
                #pragma unroll
                for (int j = 0; j < 2; ++j)
                    wmma::mma_sync(acc[i][j], a[i], bb[j], acc[i][j]);
        }
        __syncthreads();
    }
    #pragma unroll
    for (int i = 0; i < 2; ++i)
        #pragma unroll
        for (int j = 0; j < 2; ++j) {
            float* p = g_P + (size_t)(m0 + wm * 32 + i * 16) * NGATES + (n0 + wn * 32 + j * 16);
            wmma::store_matrix_sync(p, acc[i][j], NGATES, wmma::mem_row_major);
        }
}

// ---------------- per-timestep kernel ----------------
// Each CTA owns 8 hidden units (all 4 gates = 32 gate-rows), full K=1024.
// R[64 batch][32 gate-rows] = h_{t-1} @ W^T  then fused LSTM pointwise epilogue.
__global__ void __launch_bounds__(256) step_kernel(
    float* __restrict__ out, int t,
    const float* __restrict__ Wfh, const float* __restrict__ Wih,
    const float* __restrict__ Wgh, const float* __restrict__ Woh,
    const float* __restrict__ bfx, const float* __restrict__ bfh,
    const float* __restrict__ bix, const float* __restrict__ bih,
    const float* __restrict__ bgx, const float* __restrict__ bgh,
    const float* __restrict__ boxp, const float* __restrict__ boh)
{
    constexpr int BK = 64;
    __shared__ __align__(16) float As[2][NBATCH][BK];  // h tile: 64 x 64
    __shared__ __align__(16) float Bs[2][32][BK];      // 32 gate-rows x 64

    const int tid = threadIdx.x;
    const int u0 = blockIdx.x * 8;  // 128 CTAs * 8 units

    const float* hprev = (t == 0) ? g_h0 : (out + (size_t)(t - 1) * NBATCH * HSZ);

    auto load_chunk = [&](int st, int k0) {
        #pragma unroll
        for (int j = 0; j < 4; ++j) {                  // A: 64 rows x 16 vec4
            int idx = tid + j * 256;                   // 0..1023
            int r = idx >> 4, c = (idx & 15) * 4;
            cp16(&As[st][r][c], hprev + (size_t)r * HSZ + k0 + c);
        }
        #pragma unroll
        for (int j = 0; j < 2; ++j) {                  // B: 32 rows x 16 vec4
            int idx = tid + j * 256;                   // 0..511
            int r = idx >> 4, c = (idx & 15) * 4;
            int g = r >> 3, ul = r & 7;
            const float* Wg = (g == 0) ? Wfh : (g == 1) ? Wih : (g == 2) ? Wgh : Woh;
            cp16(&Bs[st][r][c], Wg + (size_t)(u0 + ul) * HSZ + k0 + c);
        }
        cp_commit();
    };

    const int wid = tid >> 5;
    const int wm = wid & 3;   // batch rows wm*16..+16
    const int wn = wid >> 2;  // gate-cols wn*16..+16

    wmma::fragment<wmma::accumulator, 16, 16, 8, float> acc0, acc1;
    wmma::fill_fragment(acc0, 0.f);
    wmma::fill_fragment(acc1, 0.f);

    constexpr int NIT = HSZ / BK;  // 16
    load_chunk(0, 0);
    for (int kt = 0; kt < NIT; ++kt) {
        int cur = kt & 1;
        if (kt + 1 < NIT) { load_chunk(cur ^ 1, (kt + 1) * BK); cp_wait<1>(); }
        else              { cp_wait<0>(); }
        __syncthreads();
        #pragma unroll
        for (int kk = 0; kk < BK / 8; ++kk) {
            wmma::fragment<wmma::matrix_a, 16, 16, 8, wmma::precision::tf32, wmma::row_major> a;
            wmma::fragment<wmma::matrix_b, 16, 16, 8, wmma::precision::tf32, wmma::col_major> bb;
            wmma::load_matrix_sync(a, &As[cur][wm * 16][kk * 8], BK);
            #pragma unroll
            for (int e = 0; e < a.num_elements; ++e) a.x[e] = wmma::__float_to_tf32(a.x[e]);
            wmma::load_matrix_sync(bb, &Bs[cur][wn * 16][kk * 8], BK);
            #pragma unroll
            for (int e = 0; e < bb.num_elements; ++e) bb.x[e] = wmma::__float_to_tf32(bb.x[e]);
            if (kk & 1) wmma::mma_sync(acc1, a, bb, acc1);
            else        wmma::mma_sync(acc0, a, bb, acc0);
        }
        __syncthreads();
    }
    #pragma unroll
    for (int e = 0; e < acc0.num_elements; ++e) acc0.x[e] += acc1.x[e];

    // Stash R into smem (alias the A buffer — all GEMM reads done).
    float* Rs = &As[0][0][0];  // treated as [64][32]
    wmma::store_matrix_sync(&Rs[(wm * 16) * 32 + wn * 16], acc0, 32, wmma::mem_row_major);
    __syncthreads();

    float* hout = out + (size_t)t * NBATCH * HSZ;
    #pragma unroll
    for (int j = 0; j < 2; ++j) {
        int idx = tid + j * 256;          // 0..511 -> (batch, unit_local)
        int b  = idx >> 3;
        int ul = idx & 7;
        int u  = u0 + ul;
        const float* Pp = g_P + ((size_t)t * NBATCH + b) * NGATES + u;
        float pf = Rs[b * 32 +      ul] + Pp[0]        + bfx[u]  + bfh[u];
        float pi = Rs[b * 32 +  8 + ul] + Pp[HSZ]      + bix[u]  + bih[u];
        float pg = Rs[b * 32 + 16 + ul] + Pp[2 * HSZ]  + bgx[u]  + bgh[u];
        float po = Rs[b * 32 + 24 + ul] + Pp[3 * HSZ]  + boxp[u] + boh[u];
        float f  = 1.f / (1.f + expf(-pf));
        float ii = 1.f / (1.f + expf(-pi));
        float gg = tanhf(pg);
        float oo = 1.f / (1.f + expf(-po));
        float cc = g_c[b * HSZ + u] * f + ii * gg;
        g_c[b * HSZ + u] = cc;
        hout[(size_t)b * HSZ + u] = tanhf(cc) * oo;
    }
}

// ---------------- finalize: copy h_final and c_final ----------------
__global__ void fin_kernel(float* __restrict__ out) {
    int i = blockIdx.x * blockDim.x + threadIdx.x;
    if (i < NBATCH * HSZ) {
        out[(size_t)SEQL * NBATCH * HSZ + i] = out[(size_t)(SEQL - 1) * NBATCH * HSZ + i];
        out[(size_t)SEQL * NBATCH * HSZ + NBATCH * HSZ + i] = g_c[i];
    }
}

extern "C" void kernel_launch(void* const* d_in, const int* in_sizes, int n_in,
                              void* d_out, int out_size) {
    const float* x    = (const float*)d_in[0];
    const float* Wfx  = (const float*)d_in[1];
    const float* bfx  = (const float*)d_in[2];
    const float* Wix  = (const float*)d_in[3];
    const float* bix  = (const float*)d_in[4];
    const float* Wgx  = (const float*)d_in[5];
    const float* bgx  = (const float*)d_in[6];
    const float* Wox  = (const float*)d_in[7];
    const float* boxp = (const float*)d_in[8];
    const float* Wfh  = (const float*)d_in[9];
    const float* bfh  = (const float*)d_in[10];
    const float* Wih  = (const float*)d_in[11];
    const float* bih  = (const float*)d_in[12];
    const float* Wgh  = (const float*)d_in[13];
    const float* bgh  = (const float*)d_in[14];
    const float* Woh  = (const float*)d_in[15];
    const float* boh  = (const float*)d_in[16];
    float* out = (float*)d_out;

    init_kernel<<<(NBATCH * HSZ + 255) / 256, 256>>>();

    dim3 g1((SEQL * NBATCH) / 128, NGATES / 64);
    xproj_kernel<<<g1, 256>>>(x, Wfx, Wix, Wgx, Wox);

    for (int t = 0; t < SEQL; ++t) {
        step_kernel<<<128, 256>>>(out, t, Wfh, Wih, Wgh, Woh,
                                  bfx, bfh, bix, bih, bgx, bgh, boxp, boh);
    }

    fin_kernel<<<(NBATCH * HSZ + 255) / 256, 256>>>(out);
}

// round 4
// speedup vs baseline: 1.0934x; 1.0934x over previous
#include <cuda_runtime.h>
#include <mma.h>
#include <cstdint>
#include <cstddef>

using namespace nvcuda;

#define SEQL 512
#define NBATCH 64
#define ISZ 256
#define HSZ 1024
#define NGATES 4096
#define NCTA 128
#define NTHR 256
#define BH (NBATCH * HSZ)

// ---------------- device scratch (no allocations allowed) ----------------
__device__ float g_P[(size_t)SEQL * NBATCH * NGATES];  // x-projections, 512MB
__device__ float g_hT[2][HSZ * NBATCH];                // transposed h ping-pong
__device__ unsigned g_count;                           // grid barrier counter

// ---------------- smem layout for persistent kernel ----------------
#define WS_OFF   0                       // 32 x 1024 fp32 weights  (131072 B)
#define HS_OFF   131072                  // 4 stages x 64x64 fp32   ( 65536 B)
#define RS_OFF   (HS_OFF + 65536)        // 64 x 32 fp32 R stash    (  8192 B)
#define BAR_OFF  (RS_OFF + 8192)         // 4 mbarriers
#define SMEM_BYTES (BAR_OFF + 64)

// ---------------- async helpers ----------------
__device__ __forceinline__ void cp16(void* smem, const void* gmem) {
    uint32_t s = (uint32_t)__cvta_generic_to_shared(smem);
    asm volatile("cp.async.cg.shared.global [%0], [%1], 16;\n" :: "r"(s), "l"(gmem));
}
__device__ __forceinline__ void cp_commit() { asm volatile("cp.async.commit_group;\n"); }
template<int N> __device__ __forceinline__ void cp_wait() {
    asm volatile("cp.async.wait_group %0;\n" :: "n"(N));
}

__device__ __forceinline__ void mbar_init(uint32_t addr, uint32_t cnt) {
    asm volatile("mbarrier.init.shared.b64 [%0], %1;\n" :: "r"(addr), "r"(cnt) : "memory");
}
__device__ __forceinline__ void mbar_expect_tx(uint32_t addr, uint32_t bytes) {
    asm volatile("mbarrier.arrive.expect_tx.shared.b64 _, [%0], %1;\n"
                 :: "r"(addr), "r"(bytes) : "memory");
}
__device__ __forceinline__ void mbar_wait(uint32_t addr, int phase) {
    asm volatile(
        "{\n\t.reg .pred P;\n\t"
        "LAB_WAIT_%=:\n\t"
        "mbarrier.try_wait.parity.acquire.cta.shared::cta.b64 P, [%0], %1, 0x989680;\n\t"
        "@P bra LAB_DONE_%=;\n\t"
        "bra LAB_WAIT_%=;\n\t"
        "LAB_DONE_%=:\n\t}"
        :: "r"(addr), "r"(phase) : "memory");
}
__device__ __forceinline__ void bulk_cp(uint32_t dst, const void* src, uint32_t bytes, uint32_t bar) {
    asm volatile(
        "cp.async.bulk.shared::cta.global.mbarrier::complete_tx::bytes [%0], [%1], %2, [%3];\n"
        :: "r"(dst), "l"(src), "r"(bytes), "r"(bar) : "memory");
}

// ---------------- init: zero grid-barrier counter ----------------
__global__ void init_kernel() {
    if (threadIdx.x == 0) g_count = 0u;
}

// ---------------- phase 1: P = x @ Wx^T (tf32 wmma) — unchanged from R2 ----------------
__global__ void __launch_bounds__(256) xproj_kernel(
    const float* __restrict__ x,
    const float* __restrict__ Wfx, const float* __restrict__ Wix,
    const float* __restrict__ Wgx, const float* __restrict__ Wox)
{
    constexpr int BM = 128, BN = 64, BK = 32;
    __shared__ __align__(16) float As[2][BM][BK];
    __shared__ __align__(16) float Bs[2][BN][BK];

    const int tid = threadIdx.x;
    const int m0 = blockIdx.x * BM;
    const int n0 = blockIdx.y * BN;

    const int gate = n0 >> 10;
    const float* Wsel = (gate == 0) ? Wfx : (gate == 1) ? Wix : (gate == 2) ? Wgx : Wox;
    const int u0 = n0 & (HSZ - 1);

    const int wid = tid >> 5;
    const int wm = wid & 3;
    const int wn = wid >> 2;

    wmma::fragment<wmma::accumulator, 16, 16, 8, float> acc[2][2];
    #pragma unroll
    for (int i = 0; i < 2; ++i)
        #pragma unroll
        for (int j = 0; j < 2; ++j) wmma::fill_fragment(acc[i][j], 0.f);

    auto load_chunk = [&](int st, int k0) {
        #pragma unroll
        for (int j = 0; j < 4; ++j) {
            int idx = tid + j * 256;
            int r = idx >> 3, c = (idx & 7) * 4;
            cp16(&As[st][r][c], x + (size_t)(m0 + r) * ISZ + k0 + c);
        }
        #pragma unroll
        for (int j = 0; j < 2; ++j) {
            int idx = tid + j * 256;
            int r = idx >> 3, c = (idx & 7) * 4;
            cp16(&Bs[st][r][c], Wsel + (size_t)(u0 + r) * ISZ + k0 + c);
        }
        cp_commit();
    };

    constexpr int NIT = ISZ / BK;
    load_chunk(0, 0);
    for (int kt = 0; kt < NIT; ++kt) {
        int cur = kt & 1;
        if (kt + 1 < NIT) { load_chunk(cur ^ 1, (kt + 1) * BK); cp_wait<1>(); }
        else              { cp_wait<0>(); }
        __syncthreads();
        #pragma unroll
        for (int kk = 0; kk < BK / 8; ++kk) {
            wmma::fragment<wmma::matrix_a, 16, 16, 8, wmma::precision::tf32, wmma::row_major> a[2];
            wmma::fragment<wmma::matrix_b, 16, 16, 8, wmma::precision::tf32, wmma::col_major> bb[2];
            #pragma unroll
            for (int i = 0; i < 2; ++i) {
                wmma::load_matrix_sync(a[i], &As[cur][wm * 32 + i * 16][kk * 8], BK);
                #pragma unroll
                for (int e = 0; e < a[i].num_elements; ++e)
                    a[i].x[e] = wmma::__float_to_tf32(a[i].x[e]);
            }
            #pragma unroll
            for (int j = 0; j < 2; ++j) {
                wmma::load_matrix_sync(bb[j], &Bs[cur][wn * 32 + j * 16][kk * 8], BK);
                #pragma unroll
                for (int e = 0; e < bb[j].num_elements; ++e)
                    bb[j].x[e] = wmma::__float_to_tf32(bb[j].x[e]);
            }
            #pragma unroll
            for (int i = 0; i < 2; ++i)
                #pragma unroll
                for (int j = 0; j < 2; ++j)
                    wmma::mma_sync(acc[i][j], a[i], bb[j], acc[i][j]);
        }
        __syncthreads();
    }
    #pragma unroll
    for (int i = 0; i < 2; ++i)
        #pragma unroll
        for (int j = 0; j < 2; ++j) {
            float* p = g_P + (size_t)(m0 + wm * 32 + i * 16) * NGATES + (n0 + wn * 32 + j * 16);
            wmma::store_matrix_sync(p, acc[i][j], NGATES, wmma::mem_row_major);
        }
}

// ---------------- phase 2: persistent recurrence ----------------
// 128 CTAs, 1/SM. CTA owns 8 hidden units x 4 gates = 32 gate-rows, weights in SMEM.
// Per step: R[64b][32n] = h_{t-1} @ W^T via tf32 wmma from hT (transposed h in L2),
// fused LSTM pointwise (c in registers), write h_seq + hT, grid spin barrier.
__global__ void __launch_bounds__(NTHR, 1) lstm_persistent(
    float* __restrict__ out,
    const float* __restrict__ Wfh, const float* __restrict__ Wih,
    const float* __restrict__ Wgh, const float* __restrict__ Woh,
    const float* __restrict__ bfx, const float* __restrict__ bfh,
    const float* __restrict__ bix, const float* __restrict__ bih,
    const float* __restrict__ bgx, const float* __restrict__ bgh,
    const float* __restrict__ boxp, const float* __restrict__ boh)
{
    extern __shared__ char smem[];
    float* Ws  = (float*)(smem + WS_OFF);   // [32][1024]
    float* hsb = (float*)(smem + HS_OFF);   // 4 stages of [64k][64b]
    float* Rs  = (float*)(smem + RS_OFF);   // [64][32]
    const uint32_t bar0 = (uint32_t)__cvta_generic_to_shared(smem + BAR_OFF);

    const int tid = threadIdx.x;
    const int u0 = blockIdx.x * 8;

    if (tid == 0) {
        #pragma unroll
        for (int s = 0; s < 4; ++s) mbar_init(bar0 + s * 8, 1);
    }
    asm volatile("fence.proxy.async.shared::cta;\n" ::: "memory");
    __syncthreads();

    // --- load weights into SMEM, pre-rounded to tf32 (float4 vectorized) ---
    #pragma unroll
    for (int i = 0; i < 32; ++i) {
        int idx = tid + i * NTHR;        // 0..8191 float4s
        int r = idx >> 8;                // gate-row 0..31
        int c4 = idx & 255;              // float4 within row
        int g = r >> 3, ul = r & 7;
        const float* Wg = (g == 0) ? Wfh : (g == 1) ? Wih : (g == 2) ? Wgh : Woh;
        float4 v = *(const float4*)(Wg + (size_t)(u0 + ul) * HSZ + c4 * 4);
        v.x = wmma::__float_to_tf32(v.x);
        v.y = wmma::__float_to_tf32(v.y);
        v.z = wmma::__float_to_tf32(v.z);
        v.w = wmma::__float_to_tf32(v.w);
        *(float4*)(Ws + r * HSZ + c4 * 4) = v;
    }
    __syncthreads();

    // --- per-thread epilogue state: biases + cell state in registers ---
    float bsf[2], bsi[2], bsg[2], bso[2], cc[2], hv[2];
    int bb_[2], uu_[2];
    #pragma unroll
    for (int j = 0; j < 2; ++j) {
        int idx = tid + j * NTHR;
        int b = idx >> 3, ul = idx & 7, u = u0 + ul;
        bb_[j] = b; uu_[j] = u;
        bsf[j] = bfx[u] + bfh[u];
        bsi[j] = bix[u] + bih[u];
        bsg[j] = bgx[u] + bgh[u];
        bso[j] = boxp[u] + boh[u];
        cc[j] = 0.f; hv[j] = 0.f;
    }

    const int wid = tid >> 5;
    const int wm = wid & 3;   // batch rows wm*16..+16
    const int wn = wid >> 2;  // gate-cols wn*16..+16

    int ph[4] = {0, 0, 0, 0};

    for (int t = 0; t < SEQL; ++t) {
        if (t > 0) {
            const float* hsrc = g_hT[(t - 1) & 1];

            // prologue: 3 chunks in flight (4 stages)
            if (tid == 0) {
                #pragma unroll
                for (int k = 0; k < 3; ++k) {
                    mbar_expect_tx(bar0 + k * 8, 16384);
                    bulk_cp((uint32_t)__cvta_generic_to_shared(hsb + k * 4096),
                            hsrc + k * 4096, 16384, bar0 + k * 8);
                }
            }

            wmma::fragment<wmma::accumulator, 16, 16, 8, float> acc0, acc1;
            wmma::fill_fragment(acc0, 0.f);
            wmma::fill_fragment(acc1, 0.f);

            #pragma unroll
            for (int kt = 0; kt < 16; ++kt) {
                const int st = kt & 3;
                mbar_wait(bar0 + st * 8, ph[st]);
                ph[st] ^= 1;
                const float* hs = hsb + st * 4096;  // [64k][64b]
                #pragma unroll
                for (int kk = 0; kk < 8; ++kk) {
                    wmma::fragment<wmma::matrix_a, 16, 16, 8, wmma::precision::tf32, wmma::col_major> a;
                    wmma::fragment<wmma::matrix_b, 16, 16, 8, wmma::precision::tf32, wmma::col_major> bfr;
                    wmma::load_matrix_sync(a, hs + (kk * 8) * 64 + wm * 16, 64);
                    #pragma unroll
                    for (int e = 0; e < a.num_elements; ++e)
                        a.x[e] = wmma::__float_to_tf32(a.x[e]);
                    // Ws pre-rounded to tf32 at load time
                    wmma::load_matrix_sync(bfr, Ws + (wn * 16) * HSZ + kt * 64 + kk * 8, HSZ);
                    if (kk & 1) wmma::mma_sync(acc1, a, bfr, acc1);
                    else        wmma::mma_sync(acc0, a, bfr, acc0);
                }
                __syncthreads();
                if (kt < 13 && tid == 0) {
                    const int ns = (kt + 3) & 3;
                    mbar_expect_tx(bar0 + ns * 8, 16384);
                    bulk_cp((uint32_t)__cvta_generic_to_shared(hsb + ns * 4096),
                            hsrc + (kt + 3) * 4096, 16384, bar0 + ns * 8);
                }
            }
            #pragma unroll
            for (int e = 0; e < acc0.num_elements; ++e) acc0.x[e] += acc1.x[e];
            wmma::store_matrix_sync(&Rs[(wm * 16) * 32 + wn * 16], acc0, 32, wmma::mem_row_major);
            __syncthreads();
        }

        // ---- fused pointwise epilogue ----
        float* hout = out + (size_t)t * BH;
        float* hTout = g_hT[t & 1];
        #pragma unroll
        for (int j = 0; j < 2; ++j) {
            int b = bb_[j], u = uu_[j], ul = u - u0;
            const float* Pp = g_P + ((size_t)t * NBATCH + b) * NGATES + u;
            float rf, ri, rg, ro;
            if (t == 0) { rf = ri = rg = ro = 0.f; }
            else {
                rf = Rs[b * 32 + ul];
                ri = Rs[b * 32 + 8 + ul];
                rg = Rs[b * 32 + 16 + ul];
                ro = Rs[b * 32 + 24 + ul];
            }
            float pf = rf + Pp[0]        + bsf[j];
            float pi = ri + Pp[HSZ]      + bsi[j];
            float pg = rg + Pp[2 * HSZ]  + bsg[j];
            float po = ro + Pp[3 * HSZ]  + bso[j];
            float f  = 1.f / (1.f + expf(-pf));
            float ii = 1.f / (1.f + expf(-pi));
            float gg = tanhf(pg);
            float oo = 1.f / (1.f + expf(-po));
            cc[j] = cc[j] * f + ii * gg;
            float h = tanhf(cc[j]) * oo;
            hv[j] = h;
            hout[(size_t)b * HSZ + u] = h;
            hTout[u * NBATCH + b] = h;
        }

        // ---- grid barrier (monotonic counter) ----
        __threadfence();
        __syncthreads();
        if (tid == 0) {
            atomicAdd(&g_count, 1u);
            const unsigned tgt = (unsigned)(t + 1) * NCTA;
            while (*(volatile unsigned*)&g_count < tgt) { }
        }
        __syncthreads();
    }

    // ---- final h and c ----
    #pragma unroll
    for (int j = 0; j < 2; ++j) {
        int b = bb_[j], u = uu_[j];
        out[(size_t)SEQL * BH + (size_t)b * HSZ + u] = hv[j];
        out[(size_t)SEQL * BH + BH + (size_t)b * HSZ + u] = cc[j];
    }
}

extern "C" void kernel_launch(void* const* d_in, const int* in_sizes, int n_in,
                              void* d_out, int out_size) {
    const float* x    = (const float*)d_in[0];
    const float* Wfx  = (const float*)d_in[1];
    const float* bfx  = (const float*)d_in[2];
    const float* Wix  = (const float*)d_in[3];
    const float* bix  = (const float*)d_in[4];
    const float* Wgx  = (const float*)d_in[5];
    const float* bgx  = (const float*)d_in[6];
    const float* Wox  = (const float*)d_in[7];
    const float* boxp = (const float*)d_in[8];
    const float* Wfh  = (const float*)d_in[9];
    const float* bfh  = (const float*)d_in[10];
    const float* Wih  = (const float*)d_in[11];
    const float* bih  = (const float*)d_in[12];
    const float* Wgh  = (const float*)d_in[13];
    const float* bgh  = (const float*)d_in[14];
    const float* Woh  = (const float*)d_in[15];
    const float* boh  = (const float*)d_in[16];
    float* out = (float*)d_out;

    cudaFuncSetAttribute(lstm_persistent,
                         cudaFuncAttributeMaxDynamicSharedMemorySize, SMEM_BYTES);

    init_kernel<<<1, 32>>>();

    dim3 g1((SEQL * NBATCH) / 128, NGATES / 64);
    xproj_kernel<<<g1, 256>>>(x, Wfx, Wix, Wgx, Wox);

    lstm_persistent<<<NCTA, NTHR, SMEM_BYTES>>>(out, Wfh, Wih, Wgh, Woh,
                                                bfx, bfh, bix, bih,
                                                bgx, bgh, boxp, boh);
}

// round 5
// speedup vs baseline: 2.4994x; 2.2860x over previous
#include <cuda_runtime.h>
#include <mma.h>
#include <cstdint>
#include <cstddef>

using namespace nvcuda;

#define SEQL 512
#define NBATCH 64
#define ISZ 256
#define HSZ 1024
#define NGATES 4096
#define NCTA 128
#define NTHR 256
#define BH (NBATCH * HSZ)

// ---------------- device scratch (no allocations allowed) ----------------
__device__ float g_P[(size_t)SEQL * NBATCH * NGATES];  // x-projections, 512MB
__device__ float g_hT[2][HSZ * NBATCH];                // transposed h ping-pong
__device__ unsigned g_count;                           // grid barrier counter

// ---------------- persistent-kernel smem layout ----------------
// Per-warp stage area: 2 buffers of [32 k][68 floats] = 2 * 8704 B = 17408 B.
// Weight staging at init reuses the same area (16384 B <= 17408 B).
#define BUF_FLOATS (32 * 68)            // 2176 floats = 8704 B
#define WARP_STAGE_FLOATS (2 * BUF_FLOATS)
#define STAGE_FLOATS (8 * WARP_STAGE_FLOATS)   // 34816 floats = 139264 B
#define PS_FLOATS (8 * 64 * 32)                // 16384 floats = 65536 B
#define SMEM_FLOATS (STAGE_FLOATS + PS_FLOATS)
#define SMEM_BYTES (SMEM_FLOATS * 4)           // 204800 B

// ---------------- cp.async helpers ----------------
__device__ __forceinline__ void cp16(void* smem_p, const void* gmem) {
    uint32_t s = (uint32_t)__cvta_generic_to_shared(smem_p);
    asm volatile("cp.async.cg.shared.global [%0], [%1], 16;\n" :: "r"(s), "l"(gmem));
}
__device__ __forceinline__ void cp_commit() { asm volatile("cp.async.commit_group;\n"); }
template<int N> __device__ __forceinline__ void cp_wait() {
    asm volatile("cp.async.wait_group %0;\n" :: "n"(N));
}

// ---------------- init ----------------
__global__ void init_kernel() {
    if (threadIdx.x == 0) g_count = 0u;
}

// ---------------- phase 1: P = x @ Wx^T (tf32 wmma, padded smem ldm=36) ----------------
#define XA(st, r, c) xsm[(st) * (128 * 36) + (r) * 36 + (c)]
#define XB(st, r, c) xsm[9216 + (st) * (64 * 36) + (r) * 36 + (c)]
#define XPROJ_SMEM ((9216 + 2 * 64 * 36) * 4)   // 55296 B

__global__ void __launch_bounds__(256) xproj_kernel(
    const float* __restrict__ x,
    const float* __restrict__ Wfx, const float* __restrict__ Wix,
    const float* __restrict__ Wgx, const float* __restrict__ Wox)
{
    constexpr int BM = 128, BN = 64, BK = 32;
    extern __shared__ float xsm[];

    const int tid = threadIdx.x;
    const int m0 = blockIdx.x * BM;
    const int n0 = blockIdx.y * BN;

    const int gate = n0 >> 10;
    const float* Wsel = (gate == 0) ? Wfx : (gate == 1) ? Wix : (gate == 2) ? Wgx : Wox;
    const int u0 = n0 & (HSZ - 1);

    const int wid = tid >> 5;
    const int wm = wid & 3;
    const int wn = wid >> 2;

    wmma::fragment<wmma::accumulator, 16, 16, 8, float> acc[2][2];
    #pragma unroll
    for (int i = 0; i < 2; ++i)
        #pragma unroll
        for (int j = 0; j < 2; ++j) wmma::fill_fragment(acc[i][j], 0.f);

    auto load_chunk = [&](int st, int k0) {
        #pragma unroll
        for (int j = 0; j < 4; ++j) {
            int idx = tid + j * 256;
            int r = idx >> 3, c = (idx & 7) * 4;
            cp16(&XA(st, r, c), x + (size_t)(m0 + r) * ISZ + k0 + c);
        }
        #pragma unroll
        for (int j = 0; j < 2; ++j) {
            int idx = tid + j * 256;
            int r = idx >> 3, c = (idx & 7) * 4;
            cp16(&XB(st, r, c), Wsel + (size_t)(u0 + r) * ISZ + k0 + c);
        }
        cp_commit();
    };

    constexpr int NIT = ISZ / BK;
    load_chunk(0, 0);
    for (int kt = 0; kt < NIT; ++kt) {
        int cur = kt & 1;
        if (kt + 1 < NIT) { load_chunk(cur ^ 1, (kt + 1) * BK); cp_wait<1>(); }
        else              { cp_wait<0>(); }
        __syncthreads();
        #pragma unroll
        for (int kk = 0; kk < BK / 8; ++kk) {
            wmma::fragment<wmma::matrix_a, 16, 16, 8, wmma::precision::tf32, wmma::row_major> a[2];
            wmma::fragment<wmma::matrix_b, 16, 16, 8, wmma::precision::tf32, wmma::col_major> bb[2];
            #pragma unroll
            for (int i = 0; i < 2; ++i) {
                wmma::load_matrix_sync(a[i], &XA(cur, wm * 32 + i * 16, kk * 8), 36);
                #pragma unroll
                for (int e = 0; e < a[i].num_elements; ++e)
                    a[i].x[e] = wmma::__float_to_tf32(a[i].x[e]);
            }
            #pragma unroll
            for (int j = 0; j < 2; ++j) {
                wmma::load_matrix_sync(bb[j], &XB(cur, wn * 32 + j * 16, kk * 8), 36);
                #pragma unroll
                for (int e = 0; e < bb[j].num_elements; ++e)
                    bb[j].x[e] = wmma::__float_to_tf32(bb[j].x[e]);
            }
            #pragma unroll
            for (int i = 0; i < 2; ++i)
                #pragma unroll
                for (int j = 0; j < 2; ++j)
                    wmma::mma_sync(acc[i][j], a[i], bb[j], acc[i][j]);
        }
        __syncthreads();
    }
    #pragma unroll
    for (int i = 0; i < 2; ++i)
        #pragma unroll
        for (int j = 0; j < 2; ++j) {
            float* p = g_P + (size_t)(m0 + wm * 32 + i * 16) * NGATES + (n0 + wn * 32 + j * 16);
            wmma::store_matrix_sync(p, acc[i][j], NGATES, wmma::mem_row_major);
        }
}

// ---------------- phase 2: persistent recurrence ----------------
// 128 CTAs (1/SM), 8 warps. Warp w owns K-slice [w*128, w*128+128).
// B (weights) live in REGISTERS: 2 n-frags x 16 k-frags, loaded once.
// A (h_{t-1}, transposed [k][b]) streamed per-warp via cp.async double buffer
// with padded stride 68 (conflict-free wmma loads). Cross-warp K-reduction in
// smem, fused LSTM pointwise epilogue, grid spin barrier between steps.
__global__ void __launch_bounds__(NTHR, 1) lstm_persistent(
    float* __restrict__ out,
    const float* __restrict__ Wfh, const float* __restrict__ Wih,
    const float* __restrict__ Wgh, const float* __restrict__ Woh,
    const float* __restrict__ bfx, const float* __restrict__ bfh,
    const float* __restrict__ bix, const float* __restrict__ bih,
    const float* __restrict__ bgx, const float* __restrict__ bgh,
    const float* __restrict__ boxp, const float* __restrict__ boh)
{
    extern __shared__ float smf[];
    float* Ps = smf + STAGE_FLOATS;   // [8][64][32] partials; Ps also serves as Rs

    const int tid = threadIdx.x;
    const int lane = tid & 31;
    const int w = tid >> 5;
    const int u0 = blockIdx.x * 8;
    const int kbase = w * 128;

    float* buf0 = smf + w * WARP_STAGE_FLOATS;
    float* buf1 = buf0 + BUF_FLOATS;

    // ---- stage my warp's weight slice [32 n][128 k] into buf area, load B frags ----
    {
        float* wst = buf0;  // 16384 B <= 17408 B
        #pragma unroll
        for (int i = 0; i < 32; ++i) {
            int idx = lane + i * 32;      // 0..1023 float4s
            int n = idx >> 5, c4 = idx & 31;
            int g = n >> 3, ul = n & 7;
            const float* Wg = (g == 0) ? Wfh : (g == 1) ? Wih : (g == 2) ? Wgh : Woh;
            cp16(wst + n * 128 + c4 * 4,
                 Wg + (size_t)(u0 + ul) * HSZ + kbase + c4 * 4);
        }
        cp_commit();
        cp_wait<0>();
        __syncwarp();
    }
    wmma::fragment<wmma::matrix_b, 16, 16, 8, wmma::precision::tf32, wmma::col_major> bfr[2][16];
    #pragma unroll
    for (int nj = 0; nj < 2; ++nj)
        #pragma unroll
        for (int kf = 0; kf < 16; ++kf) {
            wmma::load_matrix_sync(bfr[nj][kf], buf0 + nj * 16 * 128 + kf * 8, 128);
            #pragma unroll
            for (int e = 0; e < bfr[nj][kf].num_elements; ++e)
                bfr[nj][kf].x[e] = wmma::__float_to_tf32(bfr[nj][kf].x[e]);
        }
    __syncthreads();

    // ---- per-thread epilogue state ----
    float bsf[2], bsi[2], bsg[2], bso[2], cc[2], hv[2];
    #pragma unroll
    for (int j = 0; j < 2; ++j) {
        int idx = tid + j * NTHR;
        int u = u0 + (idx & 7);
        bsf[j] = bfx[u] + bfh[u];
        bsi[j] = bix[u] + bih[u];
        bsg[j] = bgx[u] + bgh[u];
        bso[j] = boxp[u] + boh[u];
        cc[j] = 0.f; hv[j] = 0.f;
    }

    #pragma unroll 1
    for (int t = 0; t < SEQL; ++t) {
        if (t > 0) {
            const float* hsrc = g_hT[(t - 1) & 1];

            auto issue_sub = [&](float* dst, int sc) {
                const float* src = hsrc + (size_t)(kbase + sc * 32) * NBATCH;
                #pragma unroll
                for (int i = 0; i < 16; ++i) {
                    int idx = lane + i * 32;       // 0..511 float4s
                    int r = idx >> 4, c4 = idx & 15;
                    cp16(dst + r * 68 + c4 * 4, src + r * NBATCH + c4 * 4);
                }
                cp_commit();
            };

            issue_sub(buf0, 0);
            issue_sub(buf1, 1);

            wmma::fragment<wmma::accumulator, 16, 16, 8, float> acc[4][2];
            #pragma unroll
            for (int mi = 0; mi < 4; ++mi)
                #pragma unroll
                for (int nj = 0; nj < 2; ++nj) wmma::fill_fragment(acc[mi][nj], 0.f);

            #pragma unroll
            for (int sc = 0; sc < 4; ++sc) {
                if (sc < 3) cp_wait<1>(); else cp_wait<0>();
                __syncwarp();
                const float* bp = (sc & 1) ? buf1 : buf0;
                #pragma unroll
                for (int kk = 0; kk < 4; ++kk) {
                    const int kg = sc * 4 + kk;
                    wmma::fragment<wmma::matrix_a, 16, 16, 8, wmma::precision::tf32, wmma::col_major> am[4];
                    #pragma unroll
                    for (int mi = 0; mi < 4; ++mi) {
                        wmma::load_matrix_sync(am[mi], bp + (kk * 8) * 68 + mi * 16, 68);
                        #pragma unroll
                        for (int e = 0; e < am[mi].num_elements; ++e)
                            am[mi].x[e] = wmma::__float_to_tf32(am[mi].x[e]);
                    }
                    #pragma unroll
                    for (int mi = 0; mi < 4; ++mi)
                        #pragma unroll
                        for (int nj = 0; nj < 2; ++nj)
                            wmma::mma_sync(acc[mi][nj], am[mi], bfr[nj][kg], acc[mi][nj]);
                }
                if (sc < 2) issue_sub((sc & 1) ? buf1 : buf0, sc + 2);
            }

            // store partials [w][64][32]
            #pragma unroll
            for (int mi = 0; mi < 4; ++mi)
                #pragma unroll
                for (int nj = 0; nj < 2; ++nj)
                    wmma::store_matrix_sync(Ps + w * 2048 + (mi * 16) * 32 + nj * 16,
                                            acc[mi][nj], 32, wmma::mem_row_major);
            __syncthreads();

            // K-reduction across 8 warps (in place into Ps[0..2047])
            #pragma unroll
            for (int j2 = 0; j2 < 8; ++j2) {
                int e = tid + j2 * NTHR;
                float s = Ps[e];
                #pragma unroll
                for (int p = 1; p < 8; ++p) s += Ps[p * 2048 + e];
                Ps[e] = s;
            }
            __syncthreads();
        }

        // ---- fused pointwise epilogue ----
        float* hout = out + (size_t)t * BH;
        float* hTout = g_hT[t & 1];
        #pragma unroll
        for (int j = 0; j < 2; ++j) {
            int idx = tid + j * NTHR;
            int b = idx >> 3, ul = idx & 7, u = u0 + ul;
            const float* Pp = g_P + ((size_t)t * NBATCH + b) * NGATES + u;
            float rf, ri, rg, ro;
            if (t == 0) { rf = ri = rg = ro = 0.f; }
            else {
                rf = Ps[b * 32 + ul];
                ri = Ps[b * 32 + 8 + ul];
                rg = Ps[b * 32 + 16 + ul];
                ro = Ps[b * 32 + 24 + ul];
            }
            float pf = rf + Pp[0]       + bsf[j];
            float pi = ri + Pp[HSZ]     + bsi[j];
            float pg = rg + Pp[2 * HSZ] + bsg[j];
            float po = ro + Pp[3 * HSZ] + bso[j];
            float f  = 1.f / (1.f + expf(-pf));
            float ii = 1.f / (1.f + expf(-pi));
            float gg = tanhf(pg);
            float oo = 1.f / (1.f + expf(-po));
            cc[j] = cc[j] * f + ii * gg;
            float h = tanhf(cc[j]) * oo;
            hv[j] = h;
            hout[(size_t)b * HSZ + u] = h;
            hTout[u * NBATCH + b] = h;
        }

        // ---- grid barrier (monotonic counter) ----
        __threadfence();
        __syncthreads();
        if (tid == 0) {
            atomicAdd(&g_count, 1u);
            const unsigned tgt = (unsigned)(t + 1) * NCTA;
            while (*(volatile unsigned*)&g_count < tgt) { }
        }
        __syncthreads();
    }

    // ---- final h and c ----
    #pragma unroll
    for (int j = 0; j < 2; ++j) {
        int idx = tid + j * NTHR;
        int b = idx >> 3, u = u0 + (idx & 7);
        out[(size_t)SEQL * BH + (size_t)b * HSZ + u] = hv[j];
        out[(size_t)SEQL * BH + BH + (size_t)b * HSZ + u] = cc[j];
    }
}

extern "C" void kernel_launch(void* const* d_in, const int* in_sizes, int n_in,
                              void* d_out, int out_size) {
    const float* x    = (const float*)d_in[0];
    const float* Wfx  = (const float*)d_in[1];
    const float* bfx  = (const float*)d_in[2];
    const float* Wix  = (const float*)d_in[3];
    const float* bix  = (const float*)d_in[4];
    const float* Wgx  = (const float*)d_in[5];
    const float* bgx  = (const float*)d_in[6];
    const float* Wox  = (const float*)d_in[7];
    const float* boxp = (const float*)d_in[8];
    const float* Wfh  = (const float*)d_in[9];
    const float* bfh  = (const float*)d_in[10];
    const float* Wih  = (const float*)d_in[11];
    const float* bih  = (const float*)d_in[12];
    const float* Wgh  = (const float*)d_in[13];
    const float* bgh  = (const float*)d_in[14];
    const float* Woh  = (const float*)d_in[15];
    const float* boh  = (const float*)d_in[16];
    float* out = (float*)d_out;

    cudaFuncSetAttribute(xproj_kernel,
                         cudaFuncAttributeMaxDynamicSharedMemorySize, XPROJ_SMEM);
    cudaFuncSetAttribute(lstm_persistent,
                         cudaFuncAttributeMaxDynamicSharedMemorySize, SMEM_BYTES);

    init_kernel<<<1, 32>>>();

    dim3 g1((SEQL * NBATCH) / 128, NGATES / 64);
    xproj_kernel<<<g1, 256, XPROJ_SMEM>>>(x, Wfx, Wix, Wgx, Wox);

    lstm_persistent<<<NCTA, NTHR, SMEM_BYTES>>>(out, Wfh, Wih, Wgh, Woh,
                                                bfx, bfh, bix, bih,
                                                bgx, bgh, boxp, boh);
}

// round 7
// speedup vs baseline: 2.7391x; 1.0959x over previous
#include <cuda_runtime.h>
#include <mma.h>
#include <cstdint>
#include <cstddef>

using namespace nvcuda;

#define SEQL 512
#define NBATCH 64
#define ISZ 256
#define HSZ 1024
#define NGATES 4096
#define NCTA 128
#define NTHR 256
#define BH (NBATCH * HSZ)

// ---------------- device scratch (no allocations allowed) ----------------
__device__ float g_P[(size_t)SEQL * NBATCH * NGATES];  // x-projections, 512MB
__device__ float g_hT[2][HSZ * NBATCH];                // transposed h ping-pong
__device__ unsigned g_count;                           // grid barrier counter

// ---------------- persistent-kernel smem layout (floats) ----------------
// Per-warp: 4 buffers of [16 k][68 floats] = 4*1088 floats (17408 B).
// Weight staging at init reuses the same area (16384 B <= 17408 B).
#define BUF_FLOATS 1088                      // 16*68
#define WARP_STAGE_FLOATS (4 * BUF_FLOATS)   // 4352
#define STAGE_FLOATS (8 * WARP_STAGE_FLOATS) // 34816
#define PS_STRIDE 2304                       // 64*36 padded partials (ldm mult of 4!)
#define PS_FLOATS (8 * PS_STRIDE)            // 18432
#define HST_OFF (STAGE_FLOATS + PS_FLOATS)   // 53248
#define HST_FLOATS (8 * 68)                  // 544
#define SMEM_FLOATS (HST_OFF + HST_FLOATS)   // 53792
#define SMEM_BYTES (SMEM_FLOATS * 4)         // 215168 B

// ---------------- cp.async helpers ----------------
__device__ __forceinline__ void cp16(void* smem_p, const void* gmem) {
    uint32_t s = (uint32_t)__cvta_generic_to_shared(smem_p);
    asm volatile("cp.async.cg.shared.global [%0], [%1], 16;\n" :: "r"(s), "l"(gmem));
}
__device__ __forceinline__ void cp_commit() { asm volatile("cp.async.commit_group;\n"); }
template<int N> __device__ __forceinline__ void cp_wait() {
    asm volatile("cp.async.wait_group %0;\n" :: "n"(N));
}

// sigmoid: safe at both extremes (exp overflow -> 1/(1+inf) -> 0)
__device__ __forceinline__ float fast_sigmoid(float x) {
    return __fdividef(1.f, 1.f + __expf(-x));
}
// tanh = 1 - 2/(e^{2x}+1): saturates to +1 (e=inf) and -1 (e=0), no NaN
__device__ __forceinline__ float fast_tanh(float x) {
    float e = __expf(2.f * x);
    return 1.f - __fdividef(2.f, e + 1.f);
}

// ---------------- phase 1: P = x @ Wx^T (tf32 wmma, padded smem ldm=36) ----------------
#define XA(st, r, c) xsm[(st) * (128 * 36) + (r) * 36 + (c)]
#define XB(st, r, c) xsm[9216 + (st) * (64 * 36) + (r) * 36 + (c)]
#define XPROJ_SMEM ((9216 + 2 * 64 * 36) * 4)   // 55296 B

__global__ void __launch_bounds__(256) xproj_kernel(
    const float* __restrict__ x,
    const float* __restrict__ Wfx, const float* __restrict__ Wix,
    const float* __restrict__ Wgx, const float* __restrict__ Wox)
{
    constexpr int BM = 128, BN = 64, BK = 32;
    extern __shared__ float xsm[];

    const int tid = threadIdx.x;
    // reset grid-barrier counter for the persistent kernel
    if (blockIdx.x == 0 && blockIdx.y == 0 && tid == 0) g_count = 0u;

    const int m0 = blockIdx.x * BM;
    const int n0 = blockIdx.y * BN;

    const int gate = n0 >> 10;
    const float* Wsel = (gate == 0) ? Wfx : (gate == 1) ? Wix : (gate == 2) ? Wgx : Wox;
    const int u0 = n0 & (HSZ - 1);

    const int wid = tid >> 5;
    const int wm = wid & 3;
    const int wn = wid >> 2;

    wmma::fragment<wmma::accumulator, 16, 16, 8, float> acc[2][2];
    #pragma unroll
    for (int i = 0; i < 2; ++i)
        #pragma unroll
        for (int j = 0; j < 2; ++j) wmma::fill_fragment(acc[i][j], 0.f);

    auto load_chunk = [&](int st, int k0) {
        #pragma unroll
        for (int j = 0; j < 4; ++j) {
            int idx = tid + j * 256;
            int r = idx >> 3, c = (idx & 7) * 4;
            cp16(&XA(st, r, c), x + (size_t)(m0 + r) * ISZ + k0 + c);
        }
        #pragma unroll
        for (int j = 0; j < 2; ++j) {
            int idx = tid + j * 256;
            int r = idx >> 3, c = (idx & 7) * 4;
            cp16(&XB(st, r, c), Wsel + (size_t)(u0 + r) * ISZ + k0 + c);
        }
        cp_commit();
    };

    constexpr int NIT = ISZ / BK;
    load_chunk(0, 0);
    for (int kt = 0; kt < NIT; ++kt) {
        int cur = kt & 1;
        if (kt + 1 < NIT) { load_chunk(cur ^ 1, (kt + 1) * BK); cp_wait<1>(); }
        else              { cp_wait<0>(); }
        __syncthreads();
        #pragma unroll
        for (int kk = 0; kk < BK / 8; ++kk) {
            wmma::fragment<wmma::matrix_a, 16, 16, 8, wmma::precision::tf32, wmma::row_major> a[2];
            wmma::fragment<wmma::matrix_b, 16, 16, 8, wmma::precision::tf32, wmma::col_major> bb[2];
            #pragma unroll
            for (int i = 0; i < 2; ++i) {
                wmma::load_matrix_sync(a[i], &XA(cur, wm * 32 + i * 16, kk * 8), 36);
                #pragma unroll
                for (int e = 0; e < a[i].num_elements; ++e)
                    a[i].x[e] = wmma::__float_to_tf32(a[i].x[e]);
            }
            #pragma unroll
            for (int j = 0; j < 2; ++j) {
                wmma::load_matrix_sync(bb[j], &XB(cur, wn * 32 + j * 16, kk * 8), 36);
                #pragma unroll
                for (int e = 0; e < bb[j].num_elements; ++e)
                    bb[j].x[e] = wmma::__float_to_tf32(bb[j].x[e]);
            }
            #pragma unroll
            for (int i = 0; i < 2; ++i)
                #pragma unroll
                for (int j = 0; j < 2; ++j)
                    wmma::mma_sync(acc[i][j], a[i], bb[j], acc[i][j]);
        }
        __syncthreads();
    }
    #pragma unroll
    for (int i = 0; i < 2; ++i)
        #pragma unroll
        for (int j = 0; j < 2; ++j) {
            float* p = g_P + (size_t)(m0 + wm * 32 + i * 16) * NGATES + (n0 + wn * 32 + j * 16);
            wmma::store_matrix_sync(p, acc[i][j], NGATES, wmma::mem_row_major);
        }
}

// ---------------- phase 2: persistent recurrence ----------------
__global__ void __launch_bounds__(NTHR, 1) lstm_persistent(
    float* __restrict__ out,
    const float* __restrict__ Wfh, const float* __restrict__ Wih,
    const float* __restrict__ Wgh, const float* __restrict__ Woh,
    const float* __restrict__ bfx, const float* __restrict__ bfh,
    const float* __restrict__ bix, const float* __restrict__ bih,
    const float* __restrict__ bgx, const float* __restrict__ bgh,
    const float* __restrict__ boxp, const float* __restrict__ boh)
{
    extern __shared__ float smf[];
    float* Ps  = smf + STAGE_FLOATS;   // [8 warps][64][36] partials
    float* hst = smf + HST_OFF;        // [8 u][68] h transpose stage

    const int tid = threadIdx.x;
    const int lane = tid & 31;
    const int w = tid >> 5;
    const int u0 = blockIdx.x * 8;
    const int kbase = w * 128;

    float* buf0 = smf + w * WARP_STAGE_FLOATS;
    float* buf1 = buf0 + BUF_FLOATS;
    float* buf2 = buf1 + BUF_FLOATS;
    float* buf3 = buf2 + BUF_FLOATS;

    // ---- stage my warp's weight slice [32 n][128 k], load B fragments ----
    {
        float* wst = buf0;  // 16384 B <= 17408 B per-warp stage area
        #pragma unroll
        for (int i = 0; i < 32; ++i) {
            int idx = lane + i * 32;
            int n = idx >> 5, c4 = idx & 31;
            int g = n >> 3, ul = n & 7;
            const float* Wg = (g == 0) ? Wfh : (g == 1) ? Wih : (g == 2) ? Wgh : Woh;
            cp16(wst + n * 128 + c4 * 4,
                 Wg + (size_t)(u0 + ul) * HSZ + kbase + c4 * 4);
        }
        cp_commit();
        cp_wait<0>();
        __syncwarp();
    }
    wmma::fragment<wmma::matrix_b, 16, 16, 8, wmma::precision::tf32, wmma::col_major> bfr[2][16];
    #pragma unroll
    for (int nj = 0; nj < 2; ++nj)
        #pragma unroll
        for (int kf = 0; kf < 16; ++kf) {
            wmma::load_matrix_sync(bfr[nj][kf], buf0 + nj * 16 * 128 + kf * 8, 128);
            #pragma unroll
            for (int e = 0; e < bfr[nj][kf].num_elements; ++e)
                bfr[nj][kf].x[e] = wmma::__float_to_tf32(bfr[nj][kf].x[e]);
        }
    __syncthreads();

    // ---- per-thread epilogue state ----
    float bsf[2], bsi[2], bsg[2], bso[2], cc[2], hv[2];
    #pragma unroll
    for (int j = 0; j < 2; ++j) {
        int idx = tid + j * NTHR;
        int u = u0 + (idx & 7);
        bsf[j] = bfx[u] + bfh[u];
        bsi[j] = bix[u] + bih[u];
        bsg[j] = bgx[u] + bgh[u];
        bso[j] = boxp[u] + boh[u];
        cc[j] = 0.f; hv[j] = 0.f;
    }

    #pragma unroll 1
    for (int t = 0; t < SEQL; ++t) {
        // ---- prefetch g_P for this step (hides DRAM latency under GEMM) ----
        float pre[2][4];
        #pragma unroll
        for (int j = 0; j < 2; ++j) {
            int idx = tid + j * NTHR;
            int b = idx >> 3, u = u0 + (idx & 7);
            const float* Pp = g_P + ((size_t)t * NBATCH + b) * NGATES + u;
            pre[j][0] = Pp[0];
            pre[j][1] = Pp[HSZ];
            pre[j][2] = Pp[2 * HSZ];
            pre[j][3] = Pp[3 * HSZ];
        }

        if (t > 0) {
            const float* hsrc = g_hT[(t - 1) & 1];

            auto issue16 = [&](float* dst, int c) {
                const float* src = hsrc + (size_t)(kbase + c * 16) * NBATCH;
                #pragma unroll
                for (int i = 0; i < 8; ++i) {
                    int idx = lane + i * 32;
                    int r = idx >> 4, c4 = idx & 15;
                    cp16(dst + r * 68 + c4 * 4, src + r * NBATCH + c4 * 4);
                }
                cp_commit();
            };

            issue16(buf0, 0); issue16(buf1, 1); issue16(buf2, 2);

            wmma::fragment<wmma::accumulator, 16, 16, 8, float> acc[4][2];
            #pragma unroll
            for (int mi = 0; mi < 4; ++mi)
                #pragma unroll
                for (int nj = 0; nj < 2; ++nj) wmma::fill_fragment(acc[mi][nj], 0.f);

#define GEMM_CHUNK(C, WN)                                                        \
            {                                                                    \
                cp_wait<WN>(); __syncwarp();                                     \
                const float* bp = (((C) & 3) == 0) ? buf0 :                      \
                                  (((C) & 3) == 1) ? buf1 :                      \
                                  (((C) & 3) == 2) ? buf2 : buf3;                \
                _Pragma("unroll")                                                \
                for (int kk2 = 0; kk2 < 2; ++kk2) {                              \
                    const int kg = (C) * 2 + kk2;                                \
                    wmma::fragment<wmma::matrix_a, 16, 16, 8,                    \
                        wmma::precision::tf32, wmma::col_major> am[4];           \
                    _Pragma("unroll")                                            \
                    for (int mi = 0; mi < 4; ++mi) {                             \
                        wmma::load_matrix_sync(am[mi], bp + (kk2 * 8) * 68 + mi * 16, 68); \
                        _Pragma("unroll")                                        \
                        for (int e = 0; e < am[mi].num_elements; ++e)            \
                            am[mi].x[e] = wmma::__float_to_tf32(am[mi].x[e]);    \
                    }                                                            \
                    _Pragma("unroll")                                            \
                    for (int mi = 0; mi < 4; ++mi)                               \
                        _Pragma("unroll")                                        \
                        for (int nj = 0; nj < 2; ++nj)                           \
                            wmma::mma_sync(acc[mi][nj], am[mi], bfr[nj][kg], acc[mi][nj]); \
                }                                                                \
                if ((C) < 5) {                                                   \
                    float* nb = ((((C) + 3) & 3) == 0) ? buf0 :                  \
                                ((((C) + 3) & 3) == 1) ? buf1 :                  \
                                ((((C) + 3) & 3) == 2) ? buf2 : buf3;            \
                    issue16(nb, (C) + 3);                                        \
                }                                                                \
            }
            GEMM_CHUNK(0, 2) GEMM_CHUNK(1, 2) GEMM_CHUNK(2, 2) GEMM_CHUNK(3, 2)
            GEMM_CHUNK(4, 2) GEMM_CHUNK(5, 2) GEMM_CHUNK(6, 1) GEMM_CHUNK(7, 0)
#undef GEMM_CHUNK

            // store padded partials [w][64][36]  (ldm=36: multiple of 4 — legal)
            #pragma unroll
            for (int mi = 0; mi < 4; ++mi)
                #pragma unroll
                for (int nj = 0; nj < 2; ++nj)
                    wmma::store_matrix_sync(Ps + w * PS_STRIDE + (mi * 16) * 36 + nj * 16,
                                            acc[mi][nj], 36, wmma::mem_row_major);
            __syncthreads();
        }

        // ---- fused epilogue (K-reduction merged in) ----
        float* hout = out + (size_t)t * BH;
        #pragma unroll
        for (int j = 0; j < 2; ++j) {
            int idx = tid + j * NTHR;
            int b = idx >> 3, ul = idx & 7, u = u0 + ul;
            float rf = 0.f, ri = 0.f, rg = 0.f, ro = 0.f;
            if (t > 0) {
                const int base = b * 36 + ul;
                #pragma unroll
                for (int p = 0; p < 8; ++p) {
                    const float* q = Ps + p * PS_STRIDE + base;
                    rf += q[0]; ri += q[8]; rg += q[16]; ro += q[24];
                }
            }
            float pf = rf + pre[j][0] + bsf[j];
            float pi = ri + pre[j][1] + bsi[j];
            float pg = rg + pre[j][2] + bsg[j];
            float po = ro + pre[j][3] + bso[j];
            float f  = fast_sigmoid(pf);
            float ii = fast_sigmoid(pi);
            float gg = fast_tanh(pg);
            float oo = fast_sigmoid(po);
            cc[j] = cc[j] * f + ii * gg;
            float h = fast_tanh(cc[j]) * oo;
            hv[j] = h;
            hout[(size_t)b * HSZ + u] = h;
            hst[ul * 68 + b] = h;   // conflict-free padded transpose stage
        }
        __syncthreads();

        // ---- coalesced transposed h write ----
        float* hTout = g_hT[t & 1];
        if (tid < 128) {
            int ul = tid >> 4, c4 = tid & 15;
            float4 v = *(const float4*)(hst + ul * 68 + c4 * 4);
            *(float4*)(hTout + (size_t)(u0 + ul) * NBATCH + c4 * 4) = v;
        }

        // ---- grid barrier (monotonic counter) ----
        __threadfence();
        __syncthreads();
        if (tid == 0) {
            atomicAdd(&g_count, 1u);
            const unsigned tgt = (unsigned)(t + 1) * NCTA;
            while (*(volatile unsigned*)&g_count < tgt) { }
        }
        __syncthreads();
    }

    // ---- final h and c ----
    #pragma unroll
    for (int j = 0; j < 2; ++j) {
        int idx = tid + j * NTHR;
        int b = idx >> 3, u = u0 + (idx & 7);
        out[(size_t)SEQL * BH + (size_t)b * HSZ + u] = hv[j];
        out[(size_t)SEQL * BH + BH + (size_t)b * HSZ + u] = cc[j];
    }
}

extern "C" void kernel_launch(void* const* d_in, const int* in_sizes, int n_in,
                              void* d_out, int out_size) {
    const float* x    = (const float*)d_in[0];
    const float* Wfx  = (const float*)d_in[1];
    const float* bfx  = (const float*)d_in[2];
    const float* Wix  = (const float*)d_in[3];
    const float* bix  = (const float*)d_in[4];
    const float* Wgx  = (const float*)d_in[5];
    const float* bgx  = (const float*)d_in[6];
    const float* Wox  = (const float*)d_in[7];
    const float* boxp = (const float*)d_in[8];
    const float* Wfh  = (const float*)d_in[9];
    const float* bfh  = (const float*)d_in[10];
    const float* Wih  = (const float*)d_in[11];
    const float* bih  = (const float*)d_in[12];
    const float* Wgh  = (const float*)d_in[13];
    const float* bgh  = (const float*)d_in[14];
    const float* Woh  = (const float*)d_in[15];
    const float* boh  = (const float*)d_in[16];
    float* out = (float*)d_out;

    cudaFuncSetAttribute(xproj_kernel,
                         cudaFuncAttributeMaxDynamicSharedMemorySize, XPROJ_SMEM);
    cudaFuncSetAttribute(lstm_persistent,
                         cudaFuncAttributeMaxDynamicSharedMemorySize, SMEM_BYTES);

    dim3 g1((SEQL * NBATCH) / 128, NGATES / 64);
    xproj_kernel<<<g1, 256, XPROJ_SMEM>>>(x, Wfx, Wix, Wgx, Wox);

    lstm_persistent<<<NCTA, NTHR, SMEM_BYTES>>>(out, Wfh, Wih, Wgh, Woh,
                                                bfx, bfh, bix, bih,
                                                bgx, bgh, boxp, boh);
}